// round 4
// baseline (speedup 1.0000x reference)
#include <cuda_runtime.h>

// ---------------- problem constants (fixed shapes from setup_inputs) -------
#define NB   2
#define LD   4800      // L = h0c*w0c = 60*80
#define SD   4800      // S = h1c*w1c
#define CD   256
#define W0C  80
#define H0C  60
#define W1C  80
#define H1C  60
#define THRV 0.2f
#define SIM_SCALE 0.0390625f   // 1/(C * temp) = 1/(256*0.1)

#define NLT (NB*LD)            // 9600
#define NST (NB*SD)            // 9600
#define NCONF ((size_t)NB*(size_t)LD*(size_t)SD)   // 46,080,000

// ---------------- device scratch (no allocation allowed) -------------------
__device__ float    g_sim[(size_t)NB * LD * SD];   // 184 MB
__device__ unsigned g_rmax[NLT];    // encoded float max of sim per row
__device__ unsigned g_cmax[NST];    // encoded float max of sim per col
__device__ float    g_rsum[NLT];
__device__ float    g_csum[NST];
__device__ unsigned g_crmax[NLT];   // raw bits of max conf per row (conf>=0)
__device__ unsigned g_ccmax[NST];   // raw bits of max conf per col

// monotonic float<->uint encoding (handles negatives); bottom element is 0u
__device__ __forceinline__ unsigned encf(float f) {
    unsigned u = __float_as_uint(f);
    return (u & 0x80000000u) ? ~u : (u | 0x80000000u);
}
__device__ __forceinline__ float decf(unsigned u) {
    return (u & 0x80000000u) ? __uint_as_float(u & 0x7FFFFFFFu)
                             : __uint_as_float(~u);
}

// ---------------- kernel 0: reset accumulators -----------------------------
__global__ void k_init() {
    int i = blockIdx.x * 256 + threadIdx.x;
    if (i < NLT) { g_rmax[i] = 0u; g_rsum[i] = 0.f; g_crmax[i] = 0u; }
    if (i < NST) { g_cmax[i] = 0u; g_csum[i] = 0.f; g_ccmax[i] = 0u; }
}

// ---------------- kernel 1: fp32 GEMM sim = (f0 . f1^T) * SIM_SCALE --------
// 128x128 block tile, BK=16, 256 threads, 8x8 per thread.
// Epilogue: store sim + per-row/per-col max partials -> global atomicMax.
__global__ __launch_bounds__(256, 2)
void k_gemm(const float* __restrict__ A, const float* __restrict__ B) {
    const int n  = blockIdx.z;
    const int l0 = blockIdx.y * 128;
    const int s0 = blockIdx.x * 128;

    __shared__ float As[16][128];
    __shared__ float Bs[16][128];
    __shared__ unsigned redR[128];
    __shared__ unsigned redC[128];

    const int tid = threadIdx.x;
    const int tx = tid & 15, ty = tid >> 4;
    const int lr = tid >> 2;            // 0..63
    const int lc = (tid & 3) << 2;      // 0,4,8,12

    const int ga0 = l0 + lr,  ga1 = ga0 + 64;
    const int gb0 = s0 + lr,  gb1 = gb0 + 64;
    const bool va0 = ga0 < LD, va1 = ga1 < LD;
    const bool vb0 = gb0 < SD, vb1 = gb1 < SD;

    const float* pa0 = A + ((size_t)n * LD + (va0 ? ga0 : 0)) * CD + lc;
    const float* pa1 = A + ((size_t)n * LD + (va1 ? ga1 : 0)) * CD + lc;
    const float* pb0 = B + ((size_t)n * SD + (vb0 ? gb0 : 0)) * CD + lc;
    const float* pb1 = B + ((size_t)n * SD + (vb1 ? gb1 : 0)) * CD + lc;

    float acc[8][8];
#pragma unroll
    for (int i = 0; i < 8; i++)
#pragma unroll
        for (int j = 0; j < 8; j++) acc[i][j] = 0.f;

    const float4 z4 = make_float4(0.f, 0.f, 0.f, 0.f);

    for (int k0 = 0; k0 < CD; k0 += 16) {
        float4 a0 = va0 ? *(const float4*)(pa0 + k0) : z4;
        float4 a1 = va1 ? *(const float4*)(pa1 + k0) : z4;
        float4 b0 = vb0 ? *(const float4*)(pb0 + k0) : z4;
        float4 b1 = vb1 ? *(const float4*)(pb1 + k0) : z4;
        __syncthreads();
        As[lc + 0][lr] = a0.x; As[lc + 1][lr] = a0.y;
        As[lc + 2][lr] = a0.z; As[lc + 3][lr] = a0.w;
        As[lc + 0][lr + 64] = a1.x; As[lc + 1][lr + 64] = a1.y;
        As[lc + 2][lr + 64] = a1.z; As[lc + 3][lr + 64] = a1.w;
        Bs[lc + 0][lr] = b0.x; Bs[lc + 1][lr] = b0.y;
        Bs[lc + 2][lr] = b0.z; Bs[lc + 3][lr] = b0.w;
        Bs[lc + 0][lr + 64] = b1.x; Bs[lc + 1][lr + 64] = b1.y;
        Bs[lc + 2][lr + 64] = b1.z; Bs[lc + 3][lr + 64] = b1.w;
        __syncthreads();
#pragma unroll
        for (int k = 0; k < 16; k++) {
            float4 x0 = *(const float4*)&As[k][ty * 4];
            float4 x1 = *(const float4*)&As[k][64 + ty * 4];
            float4 y0 = *(const float4*)&Bs[k][tx * 4];
            float4 y1 = *(const float4*)&Bs[k][64 + tx * 4];
            float av[8] = {x0.x, x0.y, x0.z, x0.w, x1.x, x1.y, x1.z, x1.w};
            float bv[8] = {y0.x, y0.y, y0.z, y0.w, y1.x, y1.y, y1.z, y1.w};
#pragma unroll
            for (int i = 0; i < 8; i++)
#pragma unroll
                for (int j = 0; j < 8; j++) acc[i][j] += av[i] * bv[j];
        }
    }

    // ---- epilogue ----
    int rows[8], cols[8];
#pragma unroll
    for (int i = 0; i < 4; i++) {
        rows[i]     = l0 + ty * 4 + i;
        rows[4 + i] = l0 + 64 + ty * 4 + i;
        cols[i]     = s0 + tx * 4 + i;
        cols[4 + i] = s0 + 64 + tx * 4 + i;
    }
    float sv[8][8];
#pragma unroll
    for (int i = 0; i < 8; i++)
#pragma unroll
        for (int j = 0; j < 8; j++) sv[i][j] = acc[i][j] * SIM_SCALE;

#pragma unroll
    for (int i = 0; i < 8; i++) {
        if (rows[i] >= LD) continue;
        size_t base = ((size_t)n * LD + rows[i]) * SD;
        if (cols[0] < SD) {
            float4 v = make_float4(sv[i][0], sv[i][1], sv[i][2], sv[i][3]);
            *(float4*)&g_sim[base + cols[0]] = v;
        }
        if (cols[4] < SD) {
            float4 v = make_float4(sv[i][4], sv[i][5], sv[i][6], sv[i][7]);
            *(float4*)&g_sim[base + cols[4]] = v;
        }
    }

    if (tid < 128) { redR[tid] = 0u; redC[tid] = 0u; }
    __syncthreads();
    const float NEGINF = __int_as_float(0xff800000);
#pragma unroll
    for (int i = 0; i < 8; i++) {
        if (rows[i] >= LD) continue;
        float m = NEGINF;
#pragma unroll
        for (int j = 0; j < 8; j++)
            if (cols[j] < SD) m = fmaxf(m, sv[i][j]);
        atomicMax(&redR[rows[i] - l0], encf(m));
    }
#pragma unroll
    for (int j = 0; j < 8; j++) {
        if (cols[j] >= SD) continue;
        float m = NEGINF;
#pragma unroll
        for (int i = 0; i < 8; i++)
            if (rows[i] < LD) m = fmaxf(m, sv[i][j]);
        atomicMax(&redC[cols[j] - s0], encf(m));
    }
    __syncthreads();
    if (tid < 128) {
        if (l0 + tid < LD) atomicMax(&g_rmax[n * LD + l0 + tid], redR[tid]);
        if (s0 + tid < SD) atomicMax(&g_cmax[n * SD + s0 + tid], redC[tid]);
    }
}

// ---------------- kernel 2a: row softmax denominators ----------------------
__global__ void k_rowsum() {
    const int r = blockIdx.x, n = blockIdx.y;
    const int tid = threadIdx.x, lane = tid & 31, w = tid >> 5;
    const float rm = decf(g_rmax[n * LD + r]);
    const float* p = g_sim + ((size_t)n * LD + r) * SD;
    float acc = 0.f;
    for (int c = tid; c < SD; c += 256) acc += __expf(p[c] - rm);
#pragma unroll
    for (int off = 16; off > 0; off >>= 1)
        acc += __shfl_xor_sync(0xffffffffu, acc, off);
    __shared__ float sred[8];
    if (lane == 0) sred[w] = acc;
    __syncthreads();
    if (tid == 0) {
        float t = 0.f;
#pragma unroll
        for (int i = 0; i < 8; i++) t += sred[i];
        g_rsum[n * LD + r] = t;
    }
}

// ---------------- kernel 2b: column softmax denominators -------------------
__global__ void k_colsum() {
    const int c = blockIdx.x * 128 + threadIdx.x;
    if (c >= SD) return;
    const int n = blockIdx.z;
    const int r0 = blockIdx.y * 480;
    const float cm = decf(g_cmax[n * SD + c]);
    float acc = 0.f;
    for (int r = r0; r < r0 + 480; r++)
        acc += __expf(g_sim[((size_t)n * LD + r) * SD + c] - cm);
    atomicAdd(&g_csum[n * SD + c], acc);
}

// ---------------- kernel 3: conf matrix + row/col conf maxima --------------
// block: 64 rows x 128 cols, 256 threads (8 warps, warp w -> rows w*8..w*8+7)
__global__ void k_conf(float* __restrict__ out) {
    const int n  = blockIdx.z;
    const int r0 = blockIdx.y * 64;
    const int c0 = blockIdx.x * 128;
    const int tid = threadIdx.x, w = tid >> 5, lane = tid & 31;

    int cc[4]; bool cv[4]; float cmv[4], csv[4];
    unsigned cmaxbits[4];
#pragma unroll
    for (int j = 0; j < 4; j++) {
        cc[j] = c0 + j * 32 + lane;
        cv[j] = cc[j] < SD;
        cmv[j] = cv[j] ? decf(g_cmax[n * SD + cc[j]]) : 0.f;
        csv[j] = cv[j] ? (1.f / g_csum[n * SD + cc[j]]) : 0.f;
        cmaxbits[j] = 0u;
    }

#pragma unroll 1
    for (int i = 0; i < 8; i++) {
        const int r = r0 + w * 8 + i;
        const size_t base = ((size_t)n * LD + r) * SD;
        const float rm  = decf(g_rmax[n * LD + r]);
        const float rsi = 1.f / g_rsum[n * LD + r];
        unsigned rowbits = 0u;
#pragma unroll
        for (int j = 0; j < 4; j++) {
            if (!cv[j]) continue;
            float x  = g_sim[base + cc[j]];
            float cf = __expf(x - rm) * rsi * __expf(x - cmv[j]) * csv[j];
            out[base + cc[j]] = cf;
            unsigned b = __float_as_uint(cf);
            rowbits = max(rowbits, b);
            cmaxbits[j] = max(cmaxbits[j], b);
        }
#pragma unroll
        for (int off = 16; off > 0; off >>= 1)
            rowbits = max(rowbits, __shfl_xor_sync(0xffffffffu, rowbits, off));
        if (lane == 0) atomicMax(&g_crmax[n * LD + r], rowbits);
    }

    __shared__ unsigned scol[128];
    if (tid < 128) scol[tid] = 0u;
    __syncthreads();
#pragma unroll
    for (int j = 0; j < 4; j++)
        if (cv[j]) atomicMax(&scol[j * 32 + lane], cmaxbits[j]);
    __syncthreads();
    if (tid < 128 && c0 + tid < SD)
        atomicMax(&g_ccmax[n * SD + c0 + tid], scol[tid]);
}

// ---------------- kernel 4: match extraction -------------------------------
__global__ void k_extract(float* __restrict__ out) {
    const int r = blockIdx.x, n = blockIdx.y;
    const int tid = threadIdx.x, lane = tid & 31, w = tid >> 5;
    const int idx = n * LD + r;

    float* pm = out + NCONF;            // mask_v   [NB*LD]
    float* pj = pm + NLT;               // j_ids    [NB*LD]
    float* pk = pj + NLT;               // mkpts1_c [NB*LD*2]
    float* pc = pk + 2 * NLT;           // mconf    [NB*LD]

    const int i0 = r / W0C, j0 = r % W0C;
    const bool rowvalid = (i0 >= 2) && (i0 < H0C - 2) && (j0 >= 2) && (j0 < W0C - 2);

    __shared__ int smin[8];
    int best = 0x7fffffff;

    if (rowvalid) {
        const unsigned rbits = g_crmax[idx];
        const float* crow = out + (size_t)idx * SD;
        for (int c = tid; c < SD; c += 256) {
            float v = crow[c];
            if (v > THRV && __float_as_uint(v) == rbits) {
                int i1 = c / W1C, j1 = c % W1C;
                if (i1 >= 2 && i1 < H1C - 2 && j1 >= 2 && j1 < W1C - 2 &&
                    __float_as_uint(v) == g_ccmax[n * SD + c]) {
                    best = min(best, c);
                }
            }
        }
    }
#pragma unroll
    for (int off = 16; off > 0; off >>= 1)
        best = min(best, __shfl_xor_sync(0xffffffffu, best, off));
    if (lane == 0) smin[w] = best;
    __syncthreads();
    if (tid == 0) {
        int b = 0x7fffffff;
#pragma unroll
        for (int i = 0; i < 8; i++) b = min(b, smin[i]);
        if (b == 0x7fffffff) {
            pm[idx] = 0.f; pj[idx] = 0.f;
            pk[2 * idx] = 0.f; pk[2 * idx + 1] = 0.f;
            pc[idx] = 0.f;
        } else {
            float v = out[(size_t)idx * SD + b];
            pm[idx] = 1.f;
            pj[idx] = (float)b;
            pk[2 * idx]     = (float)(b % W1C);
            pk[2 * idx + 1] = (float)(b / W1C);
            pc[idx] = v;
        }
    }
}

// ---------------- launch ----------------------------------------------------
extern "C" void kernel_launch(void* const* d_in, const int* in_sizes, int n_in,
                              void* d_out, int out_size) {
    const float* f0 = (const float*)d_in[0];
    const float* f1 = (const float*)d_in[1];
    float* out = (float*)d_out;

    k_init<<<38, 256>>>();
    {
        dim3 g(38, 38, NB);
        k_gemm<<<g, 256>>>(f0, f1);
    }
    {
        dim3 g(LD, NB);
        k_rowsum<<<g, 256>>>();
    }
    {
        dim3 g(38, 10, NB);   // 38 col tiles of 128, 10 row chunks of 480
        k_colsum<<<g, 128>>>();
    }
    {
        dim3 g(38, 75, NB);   // 128-col x 64-row tiles
        k_conf<<<g, 256>>>(out);
    }
    {
        dim3 g(LD, NB);
        k_extract<<<g, 256>>>(out);
    }
}

// round 9
// speedup vs baseline: 2.0696x; 2.0696x over previous
#include <cuda_runtime.h>
#include <cuda_bf16.h>
#include <cstdint>

// ---------------- problem constants ----------------------------------------
#define NB   2
#define LDIM 4800
#define SDIM 4800
#define CD   256
#define W0C  80
#define H0C  60
#define W1C  80
#define H1C  60
#define THRV 0.2f
#define SIM_SCALE 0.0390625f   // 1/(C*temp) = 1/(256*0.1)

#define NLT (NB*LDIM)
#define NST (NB*SDIM)
#define NCONF ((size_t)NB*(size_t)LDIM*(size_t)SDIM)

// GEMM tiling: 128x128 block tile, k-chunk 64 bf16, 8 warps (4 M x 2 N)
#define BUF_SZ 16384
#define SMEM_TOTAL (4*BUF_SZ)    // Ah, Al, Bh, Bl

// ---------------- device scratch -------------------------------------------
__device__ __align__(16) __nv_bfloat16 g_f0h[(size_t)NB*LDIM*CD];
__device__ __align__(16) __nv_bfloat16 g_f0l[(size_t)NB*LDIM*CD];
__device__ __align__(16) __nv_bfloat16 g_f1h[(size_t)NB*SDIM*CD];
__device__ __align__(16) __nv_bfloat16 g_f1l[(size_t)NB*SDIM*CD];
__device__ float g_e[(size_t)NB*LDIM*SDIM];     // exp(sim), 184 MB
__device__ float g_rsum[NLT];
__device__ float g_csum[NST];
__device__ unsigned long long g_rkey[NLT];      // (conf_bits<<32)|(SDIM-1-col)
__device__ unsigned g_ccmax[NST];

// ---------------- helpers ---------------------------------------------------
__device__ __forceinline__ unsigned smem_u32(const void* p) {
    unsigned a;
    asm("{ .reg .u64 t; cvta.to.shared.u64 t, %1; cvt.u32.u64 %0, t; }"
        : "=r"(a) : "l"(p));
    return a;
}
__device__ __forceinline__ unsigned swz(unsigned off) {
    return off ^ ((off >> 3) & 0x70);
}
#define LDSM4(r, a) \
    asm volatile("ldmatrix.sync.aligned.m8n8.x4.shared.b16 {%0,%1,%2,%3}, [%4];" \
        : "=r"((r)[0]), "=r"((r)[1]), "=r"((r)[2]), "=r"((r)[3]) : "r"(a))

__device__ __forceinline__ void mma16816(float* d, const unsigned* a,
                                         const unsigned* b) {
    asm volatile(
        "mma.sync.aligned.m16n8k16.row.col.f32.bf16.bf16.f32 "
        "{%0,%1,%2,%3}, {%4,%5,%6,%7}, {%8,%9}, {%0,%1,%2,%3};"
        : "+f"(d[0]), "+f"(d[1]), "+f"(d[2]), "+f"(d[3])
        : "r"(a[0]), "r"(a[1]), "r"(a[2]), "r"(a[3]), "r"(b[0]), "r"(b[1]));
}

// ---------------- kernel: init ---------------------------------------------
__global__ void k_init() {
    int i = blockIdx.x * 256 + threadIdx.x;
    if (i < NLT) { g_rsum[i] = 0.f; g_rkey[i] = 0ull; }
    if (i < NST) { g_csum[i] = 0.f; g_ccmax[i] = 0u; }
}

// ---------------- kernel: fp32 -> bf16 hi/lo split -------------------------
__device__ __forceinline__ unsigned pack_hi(float x, float y, float& lx, float& ly) {
    __nv_bfloat16 hx = __float2bfloat16_rn(x);
    __nv_bfloat16 hy = __float2bfloat16_rn(y);
    lx = x - __bfloat162float(hx);
    ly = y - __bfloat162float(hy);
    return ((unsigned)__bfloat16_as_ushort(hy) << 16) | (unsigned)__bfloat16_as_ushort(hx);
}
__device__ __forceinline__ unsigned pack_lo(float lx, float ly) {
    return ((unsigned)__bfloat16_as_ushort(__float2bfloat16_rn(ly)) << 16)
         | (unsigned)__bfloat16_as_ushort(__float2bfloat16_rn(lx));
}

__global__ void k_split(const float* __restrict__ f0, const float* __restrict__ f1) {
    int i = blockIdx.x * 256 + threadIdx.x;   // float4 group; 614400 total
    {
        float4 a = ((const float4*)f0)[i];
        a.x *= SIM_SCALE; a.y *= SIM_SCALE; a.z *= SIM_SCALE; a.w *= SIM_SCALE;
        float l0, l1, l2, l3;
        uint2 h, l;
        h.x = pack_hi(a.x, a.y, l0, l1);
        h.y = pack_hi(a.z, a.w, l2, l3);
        l.x = pack_lo(l0, l1);
        l.y = pack_lo(l2, l3);
        ((uint2*)g_f0h)[i] = h;
        ((uint2*)g_f0l)[i] = l;
    }
    {
        float4 a = ((const float4*)f1)[i];
        float l0, l1, l2, l3;
        uint2 h, l;
        h.x = pack_hi(a.x, a.y, l0, l1);
        h.y = pack_hi(a.z, a.w, l2, l3);
        l.x = pack_lo(l0, l1);
        l.y = pack_lo(l2, l3);
        ((uint2*)g_f1h)[i] = h;
        ((uint2*)g_f1l)[i] = l;
    }
}

// ---------------- kernel: HMMA split-bf16 GEMM + fused exp/sums ------------
// grid (38, 38, NB), 256 threads. Computes e = exp(sim) for a 128x128 tile,
// stores to g_e, accumulates row/col sums of e.
__global__ void __launch_bounds__(256, 1) k_gemm() {
    extern __shared__ char smem[];
    const unsigned sbase = smem_u32(smem);
    const int tid = threadIdx.x, wid = tid >> 5, lane = tid & 31;
    const int wm = wid & 3, wn = wid >> 2;
    const int lm = lane >> 2, lq = lane & 3;
    const int n = blockIdx.z;
    const int l0 = blockIdx.y * 128;
    const int s0 = blockIdx.x * 128;

    // ---- per-thread global load geometry (4 int4 per buffer) ----
    int rA[4], rB[4], jj[4];
#pragma unroll
    for (int i = 0; i < 4; i++) {
        int idx = tid + i * 256;
        int r = idx >> 3;
        jj[i] = idx & 7;
        rA[i] = min(l0 + r, LDIM - 1);
        rB[i] = min(s0 + r, SDIM - 1);
    }
    const int4* pAh = (const int4*)g_f0h + (size_t)n * LDIM * 32;
    const int4* pAl = (const int4*)g_f0l + (size_t)n * LDIM * 32;
    const int4* pBh = (const int4*)g_f1h + (size_t)n * SDIM * 32;
    const int4* pBl = (const int4*)g_f1l + (size_t)n * SDIM * 32;
    // generic-space smem store pointers (NOT the cvta.to.shared u32!)
    char* sptr[4];
#pragma unroll
    for (int i = 0; i < 4; i++) {
        int idx = tid + i * 256;
        sptr[i] = smem + swz((idx >> 3) * 128 + (idx & 7) * 16);
    }

    // ---- ldmatrix addresses (shared-space u32; XOR k-offset per step) ----
    unsigned aA[2], aB[4];
#pragma unroll
    for (int mf = 0; mf < 2; mf++) {
        unsigned row = wm * 32 + mf * 16 + (lane & 15);
        aA[mf] = sbase + (swz(row * 128) ^ ((lane >> 4) * 16));
    }
#pragma unroll
    for (int np = 0; np < 4; np++) {
        unsigned row = wn * 64 + np * 16 + ((lane >> 4) & 1) * 8 + (lane & 7);
        aB[np] = sbase + (swz(row * 128) ^ (((lane >> 3) & 1) * 16));
    }

    float acc[2][8][4];
#pragma unroll
    for (int mf = 0; mf < 2; mf++)
#pragma unroll
        for (int nf = 0; nf < 8; nf++)
#pragma unroll
            for (int q = 0; q < 4; q++) acc[mf][nf][q] = 0.f;

    for (int c = 0; c < 4; c++) {
        const int kq = c * 8;   // int4 offset within 32-int4 row
        int4 va[8];
#pragma unroll
        for (int i = 0; i < 4; i++) va[i]     = pAh[(size_t)rA[i] * 32 + kq + jj[i]];
#pragma unroll
        for (int i = 0; i < 4; i++) va[4 + i] = pAl[(size_t)rA[i] * 32 + kq + jj[i]];
        if (c > 0) __syncthreads();   // previous compute done before overwrite
#pragma unroll
        for (int i = 0; i < 4; i++) {
            *(int4*)(sptr[i])          = va[i];
            *(int4*)(sptr[i] + BUF_SZ) = va[4 + i];
        }
        int4 vb[8];
#pragma unroll
        for (int i = 0; i < 4; i++) vb[i]     = pBh[(size_t)rB[i] * 32 + kq + jj[i]];
#pragma unroll
        for (int i = 0; i < 4; i++) vb[4 + i] = pBl[(size_t)rB[i] * 32 + kq + jj[i]];
#pragma unroll
        for (int i = 0; i < 4; i++) {
            *(int4*)(sptr[i] + 2 * BUF_SZ) = vb[i];
            *(int4*)(sptr[i] + 3 * BUF_SZ) = vb[4 + i];
        }
        __syncthreads();

#pragma unroll
        for (int ks = 0; ks < 4; ks++) {
            const unsigned kb = ks * 32;
            unsigned ah[2][4], al[2][4], bh[4][4], bl[4][4];
#pragma unroll
            for (int mf = 0; mf < 2; mf++) {
                LDSM4(ah[mf], (aA[mf] ^ kb));
                LDSM4(al[mf], (aA[mf] ^ kb) + BUF_SZ);
            }
#pragma unroll
            for (int np = 0; np < 4; np++) {
                LDSM4(bh[np], (aB[np] ^ kb) + 2 * BUF_SZ);
                LDSM4(bl[np], (aB[np] ^ kb) + 3 * BUF_SZ);
            }
            // bh[np] = {(n0-7,k0-7),(n0-7,k8-15),(n8-15,k0-7),(n8-15,k8-15)}
#pragma unroll
            for (int mf = 0; mf < 2; mf++)
#pragma unroll
                for (int np = 0; np < 4; np++) {
                    mma16816(acc[mf][2 * np + 0], ah[mf], &bh[np][0]);
                    mma16816(acc[mf][2 * np + 1], ah[mf], &bh[np][2]);
                }
#pragma unroll
            for (int mf = 0; mf < 2; mf++)
#pragma unroll
                for (int np = 0; np < 4; np++) {
                    mma16816(acc[mf][2 * np + 0], al[mf], &bh[np][0]);
                    mma16816(acc[mf][2 * np + 1], al[mf], &bh[np][2]);
                }
#pragma unroll
            for (int mf = 0; mf < 2; mf++)
#pragma unroll
                for (int np = 0; np < 4; np++) {
                    mma16816(acc[mf][2 * np + 0], ah[mf], &bl[np][0]);
                    mma16816(acc[mf][2 * np + 1], ah[mf], &bl[np][2]);
                }
        }
    }
    __syncthreads();

    // ---- epilogue: e = exp(sim), store, fused row/col sums ----
    float* srow = (float*)smem;          // [128]
    float* scol = srow + 128;            // [128]
    if (tid < 128) { srow[tid] = 0.f; scol[tid] = 0.f; }
    __syncthreads();

    float rs[2][2] = {{0.f, 0.f}, {0.f, 0.f}};
    float cs[8][2];
#pragma unroll
    for (int nf = 0; nf < 8; nf++) { cs[nf][0] = 0.f; cs[nf][1] = 0.f; }

#pragma unroll
    for (int mf = 0; mf < 2; mf++) {
        const int row0 = l0 + wm * 32 + mf * 16 + lm;
        const int row1 = row0 + 8;
        const bool vr0 = row0 < LDIM, vr1 = row1 < LDIM;
        const size_t b0 = ((size_t)n * LDIM + row0) * SDIM;
        const size_t b1 = ((size_t)n * LDIM + row1) * SDIM;
#pragma unroll
        for (int nf = 0; nf < 8; nf++) {
            const int col = s0 + wn * 64 + nf * 8 + lq * 2;
            const bool vc = col < SDIM;
            float e0 = __expf(acc[mf][nf][0]);
            float e1 = __expf(acc[mf][nf][1]);
            float e2 = __expf(acc[mf][nf][2]);
            float e3 = __expf(acc[mf][nf][3]);
            if (vr0 & vc) *(float2*)&g_e[b0 + col] = make_float2(e0, e1);
            if (vr1 & vc) *(float2*)&g_e[b1 + col] = make_float2(e2, e3);
            if (vc) {
                rs[mf][0] += e0 + e1;
                rs[mf][1] += e2 + e3;
                float f0 = vr0 ? e0 : 0.f, f1 = vr0 ? e1 : 0.f;
                float f2 = vr1 ? e2 : 0.f, f3 = vr1 ? e3 : 0.f;
                cs[nf][0] += f0 + f2;
                cs[nf][1] += f1 + f3;
            }
        }
    }
    // row sums: reduce over the quad (lanes differing in bits 0-1)
#pragma unroll
    for (int mf = 0; mf < 2; mf++)
#pragma unroll
        for (int h = 0; h < 2; h++) {
            float v = rs[mf][h];
            v += __shfl_xor_sync(0xffffffffu, v, 1);
            v += __shfl_xor_sync(0xffffffffu, v, 2);
            if (lq == 0) atomicAdd(&srow[wm * 32 + mf * 16 + h * 8 + lm], v);
        }
    // col sums: reduce over lane bits 2-4
#pragma unroll
    for (int nf = 0; nf < 8; nf++)
#pragma unroll
        for (int p = 0; p < 2; p++) {
            float v = cs[nf][p];
            v += __shfl_xor_sync(0xffffffffu, v, 4);
            v += __shfl_xor_sync(0xffffffffu, v, 8);
            v += __shfl_xor_sync(0xffffffffu, v, 16);
            if (lm == 0) atomicAdd(&scol[wn * 64 + nf * 8 + lq * 2 + p], v);
        }
    __syncthreads();
    if (tid < 128) {
        if (l0 + tid < LDIM) atomicAdd(&g_rsum[n * LDIM + l0 + tid], srow[tid]);
        if (s0 + tid < SDIM) atomicAdd(&g_csum[n * SDIM + s0 + tid], scol[tid]);
    }
}

// ---------------- kernel: conf = e^2 * rinv * cinv + max tracking ----------
// grid (19, 75, NB), 256 threads: tile = 256 cols x 64 rows
__global__ void __launch_bounds__(256) k_conf(float* __restrict__ out) {
    __shared__ float srinv[64];
    __shared__ unsigned long long wkeys[8 * 64];
    const int n = blockIdx.z, r0 = blockIdx.y * 64, c0 = blockIdx.x * 256;
    const int tid = threadIdx.x, wid = tid >> 5, lane = tid & 31;
    const int col = c0 + tid;
    const bool cv = col < SDIM;

    if (tid < 64) srinv[tid] = 1.0f / g_rsum[n * LDIM + r0 + tid];
    __syncthreads();
    const float cinv = cv ? 1.0f / g_csum[n * SDIM + col] : 0.f;
    unsigned cmax = 0u;
    const size_t ebase = ((size_t)n * LDIM + r0) * SDIM;

    for (int rr = 0; rr < 64; rr++) {
        const size_t off = ebase + (size_t)rr * SDIM + col;
        float v = cv ? g_e[off] : 0.f;
        float cf = v * v * srinv[rr] * cinv;
        if (cv) out[off] = cf;
        unsigned b = __float_as_uint(cf);
        cmax = max(cmax, b);
        unsigned long long key =
            ((unsigned long long)b << 32) | (unsigned)(SDIM - 1 - col);
#pragma unroll
        for (int o = 16; o > 0; o >>= 1) {
            unsigned long long ok = __shfl_xor_sync(0xffffffffu, key, o);
            key = (ok > key) ? ok : key;
        }
        if (lane == 0) wkeys[wid * 64 + rr] = key;
    }
    __syncthreads();
    if (tid < 64) {
        unsigned long long k = 0ull;
#pragma unroll
        for (int w = 0; w < 8; w++) {
            unsigned long long t = wkeys[w * 64 + tid];
            k = (t > k) ? t : k;
        }
        atomicMax(&g_rkey[n * LDIM + r0 + tid], k);
    }
    if (cv) atomicMax(&g_ccmax[n * SDIM + col], cmax);
}

// ---------------- kernel: match extraction (O(L)) --------------------------
__global__ void k_extract(float* __restrict__ out) {
    int idx = blockIdx.x * 256 + threadIdx.x;
    if (idx >= NLT) return;
    const int n = idx / LDIM, r = idx - n * LDIM;

    float* pm = out + NCONF;
    float* pj = pm + NLT;
    float* pk = pj + NLT;
    float* pc = pk + 2 * NLT;

    unsigned long long key = g_rkey[idx];
    unsigned bits = (unsigned)(key >> 32);
    int c = SDIM - 1 - (int)(unsigned)(key & 0xffffffffu);
    float cf = __uint_as_float(bits);

    int i0 = r / W0C, j0 = r - i0 * W0C;
    int i1 = c / W1C, j1 = c - i1 * W1C;
    bool m = (cf > THRV)
          && (i0 >= 2) && (i0 < H0C - 2) && (j0 >= 2) && (j0 < W0C - 2)
          && (i1 >= 2) && (i1 < H1C - 2) && (j1 >= 2) && (j1 < W1C - 2)
          && (bits == g_ccmax[n * SDIM + c]);

    if (m) {
        pm[idx] = 1.f;
        pj[idx] = (float)c;
        pk[2 * idx]     = (float)j1;
        pk[2 * idx + 1] = (float)i1;
        pc[idx] = cf;
    } else {
        pm[idx] = 0.f;
        pj[idx] = 0.f;
        pk[2 * idx] = 0.f;
        pk[2 * idx + 1] = 0.f;
        pc[idx] = 0.f;
    }
}

// ---------------- launch ----------------------------------------------------
extern "C" void kernel_launch(void* const* d_in, const int* in_sizes, int n_in,
                              void* d_out, int out_size) {
    const float* f0 = (const float*)d_in[0];
    const float* f1 = (const float*)d_in[1];
    float* out = (float*)d_out;

    static int s_attr_done = 0;
    if (!s_attr_done) {
        cudaFuncSetAttribute(k_gemm, cudaFuncAttributeMaxDynamicSharedMemorySize,
                             SMEM_TOTAL);
        s_attr_done = 1;
    }

    k_init<<<38, 256>>>();
    k_split<<<2400, 256>>>(f0, f1);
    {
        dim3 g(38, 38, NB);
        k_gemm<<<g, 256, SMEM_TOTAL>>>();
    }
    {
        dim3 g(19, 75, NB);
        k_conf<<<g, 256>>>(out);
    }
    k_extract<<<38, 256>>>(out);
}

// round 11
// speedup vs baseline: 2.3640x; 1.1422x over previous
#include <cuda_runtime.h>
#include <cuda_bf16.h>
#include <cstdint>

// ---------------- problem constants ----------------------------------------
#define NB   2
#define LDIM 4800
#define SDIM 4800
#define CD   256
#define W0C  80
#define H0C  60
#define W1C  80
#define H1C  60
#define THRV 0.2f
#define SIM_SCALE 0.0390625f   // 1/(C*temp) = 1/(256*0.1)

#define NLT (NB*LDIM)
#define NST (NB*SDIM)
#define NCONF ((size_t)NB*(size_t)LDIM*(size_t)SDIM)

// GEMM tiling: 128x128 block tile, k-chunk 64 bf16, 8 warps (4 M x 2 N)
#define BUF_SZ 16384
#define STAGE_SZ (4*BUF_SZ)          // Ah, Al, Bh, Bl per stage
#define SMEM_TOTAL (2*STAGE_SZ)      // double buffered (128 KB)

// ---------------- device scratch -------------------------------------------
__device__ __align__(16) __nv_bfloat16 g_f0h[(size_t)NB*LDIM*CD];
__device__ __align__(16) __nv_bfloat16 g_f0l[(size_t)NB*LDIM*CD];
__device__ __align__(16) __nv_bfloat16 g_f1h[(size_t)NB*SDIM*CD];
__device__ __align__(16) __nv_bfloat16 g_f1l[(size_t)NB*SDIM*CD];
__device__ float g_e[(size_t)NB*LDIM*SDIM];     // exp(sim), 184 MB
__device__ float g_rsum[NLT];
__device__ float g_csum[NST];
__device__ unsigned long long g_rkey[NLT];      // (conf_bits<<32)|(SDIM-1-col)
__device__ unsigned g_ccmax[NST];

// ---------------- helpers ---------------------------------------------------
__device__ __forceinline__ unsigned smem_u32(const void* p) {
    unsigned a;
    asm("{ .reg .u64 t; cvta.to.shared.u64 t, %1; cvt.u32.u64 %0, t; }"
        : "=r"(a) : "l"(p));
    return a;
}
__device__ __forceinline__ unsigned swz(unsigned off) {
    return off ^ ((off >> 3) & 0x70);
}
#define LDSM4(r, a) \
    asm volatile("ldmatrix.sync.aligned.m8n8.x4.shared.b16 {%0,%1,%2,%3}, [%4];" \
        : "=r"((r)[0]), "=r"((r)[1]), "=r"((r)[2]), "=r"((r)[3]) : "r"(a))

#define CPA16(dst, src) \
    asm volatile("cp.async.cg.shared.global [%0], [%1], 16;" \
        :: "r"(dst), "l"(src) : "memory")
#define CPA_COMMIT() asm volatile("cp.async.commit_group;" ::: "memory")
#define CPA_WAIT1()  asm volatile("cp.async.wait_group 1;" ::: "memory")
#define CPA_WAIT0()  asm volatile("cp.async.wait_group 0;" ::: "memory")

__device__ __forceinline__ void mma16816(float* d, const unsigned* a,
                                         const unsigned* b) {
    asm volatile(
        "mma.sync.aligned.m16n8k16.row.col.f32.bf16.bf16.f32 "
        "{%0,%1,%2,%3}, {%4,%5,%6,%7}, {%8,%9}, {%0,%1,%2,%3};"
        : "+f"(d[0]), "+f"(d[1]), "+f"(d[2]), "+f"(d[3])
        : "r"(a[0]), "r"(a[1]), "r"(a[2]), "r"(a[3]), "r"(b[0]), "r"(b[1]));
}

// ---------------- kernel: init ---------------------------------------------
__global__ void k_init() {
    int i = blockIdx.x * 256 + threadIdx.x;
    if (i < NLT) { g_rsum[i] = 0.f; g_rkey[i] = 0ull; }
    if (i < NST) { g_csum[i] = 0.f; g_ccmax[i] = 0u; }
}

// ---------------- kernel: fp32 -> bf16 hi/lo split -------------------------
__device__ __forceinline__ unsigned pack_hi(float x, float y, float& lx, float& ly) {
    __nv_bfloat16 hx = __float2bfloat16_rn(x);
    __nv_bfloat16 hy = __float2bfloat16_rn(y);
    lx = x - __bfloat162float(hx);
    ly = y - __bfloat162float(hy);
    return ((unsigned)__bfloat16_as_ushort(hy) << 16) | (unsigned)__bfloat16_as_ushort(hx);
}
__device__ __forceinline__ unsigned pack_lo(float lx, float ly) {
    return ((unsigned)__bfloat16_as_ushort(__float2bfloat16_rn(ly)) << 16)
         | (unsigned)__bfloat16_as_ushort(__float2bfloat16_rn(lx));
}

__global__ void k_split(const float* __restrict__ f0, const float* __restrict__ f1) {
    int i = blockIdx.x * 256 + threadIdx.x;   // float4 group; 614400 total
    {
        float4 a = ((const float4*)f0)[i];
        a.x *= SIM_SCALE; a.y *= SIM_SCALE; a.z *= SIM_SCALE; a.w *= SIM_SCALE;
        float l0, l1, l2, l3;
        uint2 h, l;
        h.x = pack_hi(a.x, a.y, l0, l1);
        h.y = pack_hi(a.z, a.w, l2, l3);
        l.x = pack_lo(l0, l1);
        l.y = pack_lo(l2, l3);
        ((uint2*)g_f0h)[i] = h;
        ((uint2*)g_f0l)[i] = l;
    }
    {
        float4 a = ((const float4*)f1)[i];
        float l0, l1, l2, l3;
        uint2 h, l;
        h.x = pack_hi(a.x, a.y, l0, l1);
        h.y = pack_hi(a.z, a.w, l2, l3);
        l.x = pack_lo(l0, l1);
        l.y = pack_lo(l2, l3);
        ((uint2*)g_f1h)[i] = h;
        ((uint2*)g_f1l)[i] = l;
    }
}

// ---------------- kernel: HMMA split-bf16 GEMM + fused exp/sums ------------
// grid (38, 38, NB), 256 threads; cp.async double-buffered mainloop.
__global__ void __launch_bounds__(256, 1) k_gemm() {
    extern __shared__ char smem[];
    const unsigned sbase = smem_u32(smem);
    const int tid = threadIdx.x, wid = tid >> 5, lane = tid & 31;
    const int wm = wid & 3, wn = wid >> 2;
    const int lm = lane >> 2, lq = lane & 3;
    const int n = blockIdx.z;
    const int l0 = blockIdx.y * 128;
    const int s0 = blockIdx.x * 128;

    // ---- per-thread global load geometry (4 int4 per buffer) ----
    const int4* srcA[8];   // [0..3]=hi rows, [4..7]=lo rows
    const int4* srcB[8];
    unsigned dstu[4];
    {
        const int4* pAh = (const int4*)g_f0h + (size_t)n * LDIM * 32;
        const int4* pAl = (const int4*)g_f0l + (size_t)n * LDIM * 32;
        const int4* pBh = (const int4*)g_f1h + (size_t)n * SDIM * 32;
        const int4* pBl = (const int4*)g_f1l + (size_t)n * SDIM * 32;
#pragma unroll
        for (int i = 0; i < 4; i++) {
            int idx = tid + i * 256;
            int r = idx >> 3, j = idx & 7;
            int ra = min(l0 + r, LDIM - 1);
            int rb = min(s0 + r, SDIM - 1);
            srcA[i]     = pAh + (size_t)ra * 32 + j;
            srcA[4 + i] = pAl + (size_t)ra * 32 + j;
            srcB[i]     = pBh + (size_t)rb * 32 + j;
            srcB[4 + i] = pBl + (size_t)rb * 32 + j;
            dstu[i] = sbase + swz(r * 128 + j * 16);
        }
    }

    // ---- ldmatrix addresses (stage 0; add STAGE_SZ for stage 1) ----
    unsigned aA[2], aB[4];
#pragma unroll
    for (int mf = 0; mf < 2; mf++) {
        unsigned row = wm * 32 + mf * 16 + (lane & 15);
        aA[mf] = sbase + (swz(row * 128) ^ ((lane >> 4) * 16));
    }
#pragma unroll
    for (int np = 0; np < 4; np++) {
        unsigned row = wn * 64 + np * 16 + ((lane >> 4) & 1) * 8 + (lane & 7);
        aB[np] = sbase + (swz(row * 128) ^ (((lane >> 3) & 1) * 16));
    }

    float acc[2][8][4];
#pragma unroll
    for (int mf = 0; mf < 2; mf++)
#pragma unroll
        for (int nf = 0; nf < 8; nf++)
#pragma unroll
            for (int q = 0; q < 4; q++) acc[mf][nf][q] = 0.f;

    // prologue: issue chunk 0 into stage 0
#pragma unroll
    for (int i = 0; i < 4; i++) {
        CPA16(dstu[i],                      srcA[i]);
        CPA16(dstu[i] + BUF_SZ,             srcA[4 + i]);
        CPA16(dstu[i] + 2 * BUF_SZ,         srcB[i]);
        CPA16(dstu[i] + 3 * BUF_SZ,         srcB[4 + i]);
    }
    CPA_COMMIT();

    for (int c = 0; c < 4; c++) {
        if (c < 3) {
            const unsigned so = ((c + 1) & 1) * STAGE_SZ;
#pragma unroll
            for (int i = 0; i < 4; i++) {
                CPA16(dstu[i] + so,              srcA[i] + (c + 1) * 8);
                CPA16(dstu[i] + so + BUF_SZ,     srcA[4 + i] + (c + 1) * 8);
                CPA16(dstu[i] + so + 2 * BUF_SZ, srcB[i] + (c + 1) * 8);
                CPA16(dstu[i] + so + 3 * BUF_SZ, srcB[4 + i] + (c + 1) * 8);
            }
            CPA_COMMIT();
            CPA_WAIT1();
        } else {
            CPA_WAIT0();
        }
        __syncthreads();

        const unsigned st = (c & 1) * STAGE_SZ;
#pragma unroll
        for (int ks = 0; ks < 4; ks++) {
            const unsigned kb = ks * 32;
            unsigned ah[2][4], al[2][4], bh[4][4], bl[4][4];
#pragma unroll
            for (int mf = 0; mf < 2; mf++) {
                LDSM4(ah[mf], ((aA[mf] ^ kb) + st));
                LDSM4(al[mf], ((aA[mf] ^ kb) + st) + BUF_SZ);
            }
#pragma unroll
            for (int np = 0; np < 4; np++) {
                LDSM4(bh[np], ((aB[np] ^ kb) + st) + 2 * BUF_SZ);
                LDSM4(bl[np], ((aB[np] ^ kb) + st) + 3 * BUF_SZ);
            }
#pragma unroll
            for (int mf = 0; mf < 2; mf++)
#pragma unroll
                for (int np = 0; np < 4; np++) {
                    mma16816(acc[mf][2 * np + 0], ah[mf], &bh[np][0]);
                    mma16816(acc[mf][2 * np + 1], ah[mf], &bh[np][2]);
                }
#pragma unroll
            for (int mf = 0; mf < 2; mf++)
#pragma unroll
                for (int np = 0; np < 4; np++) {
                    mma16816(acc[mf][2 * np + 0], al[mf], &bh[np][0]);
                    mma16816(acc[mf][2 * np + 1], al[mf], &bh[np][2]);
                }
#pragma unroll
            for (int mf = 0; mf < 2; mf++)
#pragma unroll
                for (int np = 0; np < 4; np++) {
                    mma16816(acc[mf][2 * np + 0], ah[mf], &bl[np][0]);
                    mma16816(acc[mf][2 * np + 1], ah[mf], &bl[np][2]);
                }
        }
        __syncthreads();
    }

    // ---- epilogue: e = exp(sim), store, fused row/col sums ----
    float* srow = (float*)smem;          // [128]
    float* scol = srow + 128;            // [128]
    if (tid < 128) { srow[tid] = 0.f; scol[tid] = 0.f; }
    __syncthreads();

    float rs[2][2] = {{0.f, 0.f}, {0.f, 0.f}};
    float cs[8][2];
#pragma unroll
    for (int nf = 0; nf < 8; nf++) { cs[nf][0] = 0.f; cs[nf][1] = 0.f; }

#pragma unroll
    for (int mf = 0; mf < 2; mf++) {
        const int row0 = l0 + wm * 32 + mf * 16 + lm;
        const int row1 = row0 + 8;
        const bool vr0 = row0 < LDIM, vr1 = row1 < LDIM;
        const size_t b0 = ((size_t)n * LDIM + row0) * SDIM;
        const size_t b1 = ((size_t)n * LDIM + row1) * SDIM;
#pragma unroll
        for (int nf = 0; nf < 8; nf++) {
            const int col = s0 + wn * 64 + nf * 8 + lq * 2;
            const bool vc = col < SDIM;
            float e0 = __expf(acc[mf][nf][0]);
            float e1 = __expf(acc[mf][nf][1]);
            float e2 = __expf(acc[mf][nf][2]);
            float e3 = __expf(acc[mf][nf][3]);
            if (vr0 & vc) __stcs((float2*)&g_e[b0 + col], make_float2(e0, e1));
            if (vr1 & vc) __stcs((float2*)&g_e[b1 + col], make_float2(e2, e3));
            if (vc) {
                rs[mf][0] += e0 + e1;
                rs[mf][1] += e2 + e3;
                float f0 = vr0 ? e0 : 0.f, f1 = vr0 ? e1 : 0.f;
                float f2 = vr1 ? e2 : 0.f, f3 = vr1 ? e3 : 0.f;
                cs[nf][0] += f0 + f2;
                cs[nf][1] += f1 + f3;
            }
        }
    }
    // row sums: reduce over the quad (lanes differing in bits 0-1)
#pragma unroll
    for (int mf = 0; mf < 2; mf++)
#pragma unroll
        for (int h = 0; h < 2; h++) {
            float v = rs[mf][h];
            v += __shfl_xor_sync(0xffffffffu, v, 1);
            v += __shfl_xor_sync(0xffffffffu, v, 2);
            if (lq == 0) atomicAdd(&srow[wm * 32 + mf * 16 + h * 8 + lm], v);
        }
    // col sums: reduce over lane bits 2-4
#pragma unroll
    for (int nf = 0; nf < 8; nf++)
#pragma unroll
        for (int p = 0; p < 2; p++) {
            float v = cs[nf][p];
            v += __shfl_xor_sync(0xffffffffu, v, 4);
            v += __shfl_xor_sync(0xffffffffu, v, 8);
            v += __shfl_xor_sync(0xffffffffu, v, 16);
            if (lm == 0) atomicAdd(&scol[wn * 64 + nf * 8 + lq * 2 + p], v);
        }
    __syncthreads();
    if (tid < 128) {
        if (l0 + tid < LDIM) atomicAdd(&g_rsum[n * LDIM + l0 + tid], srow[tid]);
        if (s0 + tid < SDIM) atomicAdd(&g_csum[n * SDIM + s0 + tid], scol[tid]);
    }
}

// ---------------- kernel: conf = e^2 * rinv * cinv + max tracking ----------
// grid (19, 75, NB), 256 threads: tile = 256 cols x 64 rows.
// Row argmax via REDUX.MAX + ballot (lowest lane = lowest column on ties).
__global__ void __launch_bounds__(256) k_conf(float* __restrict__ out) {
    __shared__ float srinv[64];
    __shared__ unsigned long long wkeys[8 * 64];
    const int n = blockIdx.z, r0 = blockIdx.y * 64, c0 = blockIdx.x * 256;
    const int tid = threadIdx.x, wid = tid >> 5, lane = tid & 31;
    const int col = c0 + tid;
    const bool cv = col < SDIM;

    if (tid < 64) srinv[tid] = 1.0f / g_rsum[n * LDIM + r0 + tid];
    __syncthreads();
    const float cinv = cv ? 1.0f / g_csum[n * SDIM + col] : 0.f;
    unsigned cmax = 0u;
    const size_t ebase = ((size_t)n * LDIM + r0) * SDIM;

#pragma unroll 4
    for (int rr = 0; rr < 64; rr++) {
        const size_t off = ebase + (size_t)rr * SDIM + col;
        float v = cv ? __ldcs(&g_e[off]) : 0.f;
        float cf = v * v * srinv[rr] * cinv;
        if (cv) __stcs(&out[off], cf);
        unsigned b = __float_as_uint(cf);
        cmax = max(cmax, b);
        unsigned m = __reduce_max_sync(0xffffffffu, b);
        unsigned msk = __ballot_sync(0xffffffffu, b == m);
        int leader = __ffs(msk) - 1;
        if (lane == leader) {
            int lcol = c0 + wid * 32 + leader;
            wkeys[wid * 64 + rr] =
                ((unsigned long long)m << 32) | (unsigned)(SDIM - 1 - lcol);
        }
    }
    __syncthreads();
    if (tid < 64) {
        unsigned long long k = 0ull;
#pragma unroll
        for (int w = 0; w < 8; w++) {
            unsigned long long t = wkeys[w * 64 + tid];
            k = (t > k) ? t : k;
        }
        atomicMax(&g_rkey[n * LDIM + r0 + tid], k);
    }
    if (cv) atomicMax(&g_ccmax[n * SDIM + col], cmax);
}

// ---------------- kernel: match extraction (O(L)) --------------------------
__global__ void k_extract(float* __restrict__ out) {
    int idx = blockIdx.x * 256 + threadIdx.x;
    if (idx >= NLT) return;
    const int n = idx / LDIM, r = idx - n * LDIM;

    float* pm = out + NCONF;
    float* pj = pm + NLT;
    float* pk = pj + NLT;
    float* pc = pk + 2 * NLT;

    unsigned long long key = g_rkey[idx];
    unsigned bits = (unsigned)(key >> 32);
    int c = SDIM - 1 - (int)(unsigned)(key & 0xffffffffu);
    float cf = __uint_as_float(bits);

    int i0 = r / W0C, j0 = r - i0 * W0C;
    int i1 = c / W1C, j1 = c - i1 * W1C;
    bool m = (cf > THRV)
          && (i0 >= 2) && (i0 < H0C - 2) && (j0 >= 2) && (j0 < W0C - 2)
          && (i1 >= 2) && (i1 < H1C - 2) && (j1 >= 2) && (j1 < W1C - 2)
          && (bits == g_ccmax[n * SDIM + c]);

    if (m) {
        pm[idx] = 1.f;
        pj[idx] = (float)c;
        pk[2 * idx]     = (float)j1;
        pk[2 * idx + 1] = (float)i1;
        pc[idx] = cf;
    } else {
        pm[idx] = 0.f;
        pj[idx] = 0.f;
        pk[2 * idx] = 0.f;
        pk[2 * idx + 1] = 0.f;
        pc[idx] = 0.f;
    }
}

// ---------------- launch ----------------------------------------------------
extern "C" void kernel_launch(void* const* d_in, const int* in_sizes, int n_in,
                              void* d_out, int out_size) {
    const float* f0 = (const float*)d_in[0];
    const float* f1 = (const float*)d_in[1];
    float* out = (float*)d_out;

    static int s_attr_done = 0;
    if (!s_attr_done) {
        cudaFuncSetAttribute(k_gemm, cudaFuncAttributeMaxDynamicSharedMemorySize,
                             SMEM_TOTAL);
        s_attr_done = 1;
    }

    k_init<<<38, 256>>>();
    k_split<<<2400, 256>>>(f0, f1);
    {
        dim3 g(38, 38, NB);
        k_gemm<<<g, 256, SMEM_TOTAL>>>();
    }
    {
        dim3 g(19, 75, NB);
        k_conf<<<g, 256>>>(out);
    }
    k_extract<<<38, 256>>>(out);
}